// round 1
// baseline (speedup 1.0000x reference)
#include <cuda_runtime.h>
#include <math.h>

// Problem constants
constexpr int B_  = 256;
constexpr int N_  = 2048;
constexpr int M_  = 64;
constexpr int C_  = 512;
constexpr int PR_ = 70;   // M + 3 + SHIFT
constexpr int PW_ = 198;  // PR + 2M
constexpr float EPSF = 1e-8f;

// Output layout (floats): ntm_out, memory, read_out, new_read_w, new_write_w
constexpr size_t OUT_MEM = 65536;
constexpr size_t OUT_RO  = 33619968;
constexpr size_t OUT_RW  = 33685504;
constexpr size_t OUT_WW  = 35782656;

// ---------------- device scratch (no allocations allowed) ----------------
__device__ float g_cin [B_*768];
__device__ float g_ctrl[B_*C_];
__device__ float g_rp  [4*B_*PR_];
__device__ float g_wp  [4*B_*PW_];
__device__ float g_dot [5*(size_t)B_*N_];
__device__ float g_norm[(size_t)B_*N_];

__device__ __forceinline__ float softplusf(float x){ return x > 20.f ? x : log1pf(expf(x)); }
__device__ __forceinline__ float sigmoidf (float x){ return 1.f/(1.f+expf(-x)); }

// ---------------- small utility kernels ----------------
__global__ void concat_kernel(const float* __restrict__ A, int ca,
                              const float* __restrict__ Bp, int cb,
                              float* __restrict__ out)
{
    int w = ca + cb;
    int total = B_ * w;
    for (int i = blockIdx.x*blockDim.x + threadIdx.x; i < total; i += gridDim.x*blockDim.x) {
        int r = i / w, c = i - r*w;
        out[i] = (c < ca) ? A[r*ca + c] : Bp[r*cb + (c - ca)];
    }
}

__global__ void zero_kernel(float* __restrict__ p, int n)
{
    int i = blockIdx.x*blockDim.x + threadIdx.x;
    if (i < n) p[i] = 0.f;
}

// ---------------- SGEMM: out[256,Nc] = A[256,K] @ W[K,Nc] + bias ----------------
__global__ void sgemm_bias(const float* __restrict__ A, const float* __restrict__ W,
                           const float* __restrict__ bias, float* __restrict__ out,
                           int K, int Nc)
{
    __shared__ float As[16][64];
    __shared__ float Ws[16][64];
    int tid = threadIdx.x;
    int tx = tid & 15, ty = tid >> 4;
    int row0 = blockIdx.y * 64, col0 = blockIdx.x * 64;
    float acc[4][4] = {};
    for (int k0 = 0; k0 < K; k0 += 16) {
        #pragma unroll
        for (int i = tid; i < 1024; i += 256) {
            int m = i >> 4, kk = i & 15;
            As[kk][m] = A[(size_t)(row0 + m) * K + k0 + kk];
        }
        #pragma unroll
        for (int i = tid; i < 1024; i += 256) {
            int kk = i >> 6, n = i & 63;
            int gn = col0 + n;
            Ws[kk][n] = (gn < Nc) ? W[(size_t)(k0 + kk) * Nc + gn] : 0.f;
        }
        __syncthreads();
        #pragma unroll
        for (int kk = 0; kk < 16; kk++) {
            float4 a4 = *(const float4*)&As[kk][ty*4];
            float4 b4 = *(const float4*)&Ws[kk][tx*4];
            float a[4] = {a4.x, a4.y, a4.z, a4.w};
            float b[4] = {b4.x, b4.y, b4.z, b4.w};
            #pragma unroll
            for (int i = 0; i < 4; i++)
                #pragma unroll
                for (int j = 0; j < 4; j++) acc[i][j] += a[i]*b[j];
        }
        __syncthreads();
    }
    #pragma unroll
    for (int i = 0; i < 4; i++) {
        int gm = row0 + ty*4 + i;
        #pragma unroll
        for (int j = 0; j < 4; j++) {
            int gn = col0 + tx*4 + j;
            if (gn < Nc) out[(size_t)gm*Nc + gn] = acc[i][j] + bias[gn];
        }
    }
}

// ---------------- Pass A: mem norms + 5 key dots (4 read heads + write head 0) ----------------
// grid 512 = (b, halfN), 256 threads. Warp handles 4 rows (8 lanes/row, 8 m each).
__global__ void passA_kernel(const float* __restrict__ mem)
{
    int bc = blockIdx.x; int b = bc >> 1; int nb = (bc & 1) << 10;
    int tid = threadIdx.x;
    int wid = tid >> 5, lane = tid & 31;
    int rsl = lane >> 3, mg = lane & 7;

    float kr[5][8];
    #pragma unroll
    for (int h = 0; h < 5; h++) {
        const float* kp = (h < 4) ? (g_rp + ((size_t)h*B_ + b)*PR_) : (g_wp + (size_t)b*PW_);
        #pragma unroll
        for (int j = 0; j < 8; j++) kr[h][j] = kp[mg*8 + j];
    }

    const float* base = mem + ((size_t)b*N_ + nb)*M_;
    for (int it = 0; it < 32; ++it) {
        int r = it*32 + wid*4 + rsl;
        const float4* rp4 = (const float4*)(base + (size_t)r*M_ + mg*8);
        float4 v0 = rp4[0], v1 = rp4[1];
        float vv[8] = {v0.x, v0.y, v0.z, v0.w, v1.x, v1.y, v1.z, v1.w};
        float nrm = 0.f;
        float d[5] = {0,0,0,0,0};
        #pragma unroll
        for (int j = 0; j < 8; j++) {
            nrm += vv[j]*vv[j];
            #pragma unroll
            for (int h = 0; h < 5; h++) d[h] += vv[j]*kr[h][j];
        }
        #pragma unroll
        for (int o = 1; o < 8; o <<= 1) {
            nrm += __shfl_xor_sync(0xffffffffu, nrm, o);
            #pragma unroll
            for (int h = 0; h < 5; h++) d[h] += __shfl_xor_sync(0xffffffffu, d[h], o);
        }
        if (mg == 0) {
            size_t ix = (size_t)b*N_ + nb + r;
            g_norm[ix] = sqrtf(nrm);
            #pragma unroll
            for (int h = 0; h < 5; h++) g_dot[(size_t)h*B_*N_ + ix] = d[h];
        }
    }
}

// ---------------- block reduction helpers (256 threads) ----------------
__device__ __forceinline__ float block_reduce_sum(float v, float* sbuf)
{
    int tid = threadIdx.x;
    #pragma unroll
    for (int o = 16; o > 0; o >>= 1) v += __shfl_xor_sync(0xffffffffu, v, o);
    if ((tid & 31) == 0) sbuf[tid >> 5] = v;
    __syncthreads();
    if (tid < 32) {
        float x = (tid < 8) ? sbuf[tid] : 0.f;
        #pragma unroll
        for (int o = 4; o > 0; o >>= 1) x += __shfl_xor_sync(0xffffffffu, x, o);
        if (tid == 0) sbuf[0] = x;
    }
    __syncthreads();
    float r = sbuf[0];
    __syncthreads();
    return r;
}

__device__ __forceinline__ float block_reduce_max(float v, float* sbuf)
{
    int tid = threadIdx.x;
    #pragma unroll
    for (int o = 16; o > 0; o >>= 1) v = fmaxf(v, __shfl_xor_sync(0xffffffffu, v, o));
    if ((tid & 31) == 0) sbuf[tid >> 5] = v;
    __syncthreads();
    if (tid < 32) {
        float x = (tid < 8) ? sbuf[tid] : -3.4e38f;
        #pragma unroll
        for (int o = 4; o > 0; o >>= 1) x = fmaxf(x, __shfl_xor_sync(0xffffffffu, x, o));
        if (tid == 0) sbuf[0] = x;
    }
    __syncthreads();
    float r = sbuf[0];
    __syncthreads();
    return r;
}

// ---------------- NTM addressing: one CTA per batch element ----------------
__global__ void address_kernel(const float* __restrict__ P, int prow,
                               const float* __restrict__ dot,
                               const float* __restrict__ nrm,
                               const float* __restrict__ wprev,
                               float* __restrict__ wout)
{
    int b = blockIdx.x;
    int tid = threadIdx.x;
    const float* p = P + (size_t)b * prow;

    __shared__ float wg[2048];
    __shared__ float rbuf[32];
    __shared__ float sc[7];

    float kv = 0.f;
    if (tid < 64) { float x = p[tid]; kv = x*x; }
    float ksum = block_reduce_sum(kv, rbuf);
    if (tid == 0) {
        sc[0] = sqrtf(ksum);                    // k_norm
        sc[1] = softplusf(p[64]);               // beta
        sc[2] = sigmoidf(p[65]);                // g
        float a0 = p[66], a1 = p[67], a2 = p[68];
        float mx = fmaxf(a0, fmaxf(a1, a2));
        float e0 = expf(a0-mx), e1 = expf(a1-mx), e2 = expf(a2-mx);
        float es = e0 + e1 + e2;
        sc[3] = e0/es; sc[4] = e1/es; sc[5] = e2/es;  // s
        sc[6] = 1.f + softplusf(p[69]);         // gamma
    }
    __syncthreads();
    float knorm = sc[0], beta = sc[1], g = sc[2];
    float s0 = sc[3], s1 = sc[4], s2 = sc[5], gamma = sc[6];

    const float* dotb = dot   + (size_t)b*N_;
    const float* nrmb = nrm   + (size_t)b*N_;
    const float* wpb  = wprev + (size_t)b*N_;

    float x[8];
    float mx = -3.4e38f;
    #pragma unroll
    for (int i = 0; i < 8; i++) {
        int n = tid + i*256;
        float cosv = dotb[n] / (nrmb[n]*knorm + EPSF);
        x[i] = beta * cosv;
        mx = fmaxf(mx, x[i]);
    }
    float bmax = block_reduce_max(mx, rbuf);
    float lsum = 0.f;
    #pragma unroll
    for (int i = 0; i < 8; i++) {
        float e = expf(x[i] - bmax);
        wg[tid + i*256] = e;
        lsum += e;
    }
    float bsum = block_reduce_sum(lsum, rbuf);
    float inv = 1.f / bsum;
    #pragma unroll
    for (int i = 0; i < 8; i++) {
        int n = tid + i*256;
        wg[n] = g * (wg[n]*inv) + (1.f-g) * wpb[n];
    }
    __syncthreads();
    float wpow[8];
    lsum = 0.f;
    #pragma unroll
    for (int i = 0; i < 8; i++) {
        int n = tid + i*256;
        float ws = s0*wg[(n+1)&(N_-1)] + s1*wg[n] + s2*wg[(n-1)&(N_-1)];
        float t = powf(ws + EPSF, gamma);
        wpow[i] = t;
        lsum += t;
    }
    float psum = block_reduce_sum(lsum, rbuf);
    float ip = 1.f / psum;
    #pragma unroll
    for (int i = 0; i < 8; i++)
        wout[(size_t)b*N_ + tid + i*256] = wpow[i]*ip;
}

// ---------------- Pass B: reads einsum + head0 update + dot for head1 ----------------
// grid 512 = (b, halfN), 256 threads, warp-per-row (float2 per lane).
__global__ void passB_kernel(const float* __restrict__ mem_in, float* __restrict__ mem_out,
                             const float* __restrict__ wr,   // new_read_w [4][B][N]
                             const float* __restrict__ ww0,  // new_write_w head 0
                             float* __restrict__ read_out)   // [B,256]
{
    int bc = blockIdx.x; int b = bc >> 1; int nb = (bc & 1) << 10;
    int tid = threadIdx.x, wid = tid >> 5, lane = tid & 31;

    __shared__ float sE[64], sA[64];
    __shared__ float2 sred[8][4][32];
    if (tid < 64) {
        const float* pwb = g_wp + (size_t)b*PW_;   // head 0
        sE[tid] = sigmoidf(pwb[70 + tid]);
        sA[tid] = tanhf(pwb[134 + tid]);
    }
    const float* k1p = g_wp + ((size_t)1*B_ + b)*PW_;
    float kx = k1p[2*lane], ky = k1p[2*lane + 1];
    __syncthreads();
    float ex = sE[2*lane], ey = sE[2*lane+1];
    float ax = sA[2*lane], ay = sA[2*lane+1];

    float2 acc[4] = {{0,0},{0,0},{0,0},{0,0}};
    float* dot1 = g_dot + (size_t)4*B_*N_;

    for (int it = 0; it < 128; ++it) {
        int n = nb + it*8 + wid;
        size_t wix = (size_t)b*N_ + n;
        size_t off = wix*M_ + 2*lane;
        float2 v = *(const float2*)(mem_in + off);
        float w0 = ww0[wix];
        #pragma unroll
        for (int h = 0; h < 4; h++) {
            float wv = wr[(size_t)h*B_*N_ + wix];
            acc[h].x += wv*v.x; acc[h].y += wv*v.y;
        }
        float2 u;
        u.x = v.x*(1.f - w0*ex) + w0*ax;
        u.y = v.y*(1.f - w0*ey) + w0*ay;
        *(float2*)(mem_out + off) = u;
        float d  = u.x*kx + u.y*ky;
        float nm = u.x*u.x + u.y*u.y;
        #pragma unroll
        for (int o = 16; o > 0; o >>= 1) {
            d  += __shfl_xor_sync(0xffffffffu, d, o);
            nm += __shfl_xor_sync(0xffffffffu, nm, o);
        }
        if (lane == 0) { dot1[wix] = d; g_norm[wix] = sqrtf(nm); }
    }

    #pragma unroll
    for (int h = 0; h < 4; h++) sred[wid][h][lane] = acc[h];
    __syncthreads();
    int h = tid >> 6, l = (tid >> 1) & 31, c = tid & 1;
    float s = 0.f;
    #pragma unroll
    for (int w = 0; w < 8; w++) {
        float2 t = sred[w][h][l];
        s += c ? t.y : t.x;
    }
    atomicAdd(read_out + (size_t)b*256 + h*64 + 2*l + c, s);
}

// ---------------- Pass C/D/E: memory update in place (+ optional next-head dot) ----------------
__global__ void pass_update_kernel(float* __restrict__ memio,
                                   const float* __restrict__ ww,
                                   const float* __restrict__ pw_head,
                                   const float* __restrict__ knext,
                                   float* __restrict__ dot_out)
{
    int bc = blockIdx.x; int b = bc >> 1; int nb = (bc & 1) << 10;
    int tid = threadIdx.x, wid = tid >> 5, lane = tid & 31;

    __shared__ float sE[64], sA[64];
    if (tid < 64) {
        const float* pwb = pw_head + (size_t)b*PW_;
        sE[tid] = sigmoidf(pwb[70 + tid]);
        sA[tid] = tanhf(pwb[134 + tid]);
    }
    float kx = 0.f, ky = 0.f;
    bool do_dot = (knext != nullptr);
    if (do_dot) {
        const float* kb = knext + (size_t)b*PW_;
        kx = kb[2*lane]; ky = kb[2*lane + 1];
    }
    __syncthreads();
    float ex = sE[2*lane], ey = sE[2*lane+1];
    float ax = sA[2*lane], ay = sA[2*lane+1];

    for (int it = 0; it < 128; ++it) {
        int n = nb + it*8 + wid;
        size_t wix = (size_t)b*N_ + n;
        size_t off = wix*M_ + 2*lane;
        float2 v = *(const float2*)(memio + off);
        float w0 = ww[wix];
        float2 u;
        u.x = v.x*(1.f - w0*ex) + w0*ax;
        u.y = v.y*(1.f - w0*ey) + w0*ay;
        *(float2*)(memio + off) = u;
        if (do_dot) {
            float d  = u.x*kx + u.y*ky;
            float nm = u.x*u.x + u.y*u.y;
            #pragma unroll
            for (int o = 16; o > 0; o >>= 1) {
                d  += __shfl_xor_sync(0xffffffffu, d, o);
                nm += __shfl_xor_sync(0xffffffffu, nm, o);
            }
            if (lane == 0) { dot_out[wix] = d; g_norm[wix] = sqrtf(nm); }
        }
    }
}

// ---------------- host launcher ----------------
extern "C" void kernel_launch(void* const* d_in, const int* in_sizes, int n_in,
                              void* d_out, int out_size)
{
    const float* ext    = (const float*)d_in[0];
    const float* pread  = (const float*)d_in[1];
    const float* prw    = (const float*)d_in[2];
    const float* pww    = (const float*)d_in[3];
    const float* mem    = (const float*)d_in[4];
    const float* ctrlW  = (const float*)d_in[5];
    const float* ctrlb  = (const float*)d_in[6];
    const float* readW  = (const float*)d_in[7];
    const float* readb  = (const float*)d_in[8];
    const float* writeW = (const float*)d_in[9];
    const float* writeb = (const float*)d_in[10];
    const float* outW   = (const float*)d_in[11];
    const float* outb   = (const float*)d_in[12];
    float* out = (float*)d_out;

    float *cin, *ctrl, *rp, *wp, *dot, *nrm;
    cudaGetSymbolAddress((void**)&cin,  g_cin);
    cudaGetSymbolAddress((void**)&ctrl, g_ctrl);
    cudaGetSymbolAddress((void**)&rp,   g_rp);
    cudaGetSymbolAddress((void**)&wp,   g_wp);
    cudaGetSymbolAddress((void**)&dot,  g_dot);
    cudaGetSymbolAddress((void**)&nrm,  g_norm);

    float* o_mem = out + OUT_MEM;
    float* o_ro  = out + OUT_RO;
    float* o_rw  = out + OUT_RW;
    float* o_ww  = out + OUT_WW;

    // Controller
    concat_kernel<<<256, 256>>>(ext, 256, pread, 256, cin);
    sgemm_bias<<<dim3(8, 4), 256>>>(cin, ctrlW, ctrlb, ctrl, 512, 512);

    // Head parameter GEMMs
    for (int h = 0; h < 4; h++)
        sgemm_bias<<<dim3(2, 4), 256>>>(ctrl, readW + (size_t)h*512*PR_, readb + h*PR_,
                                        rp + (size_t)h*B_*PR_, 512, PR_);
    for (int h = 0; h < 4; h++)
        sgemm_bias<<<dim3(4, 4), 256>>>(ctrl, writeW + (size_t)h*512*PW_, writeb + h*PW_,
                                        wp + (size_t)h*B_*PW_, 512, PW_);

    // Pass A: norms + cos dots for 4 read heads + write head 0
    passA_kernel<<<512, 256>>>(mem);

    zero_kernel<<<256, 256>>>(o_ro, B_*256);

    // Addressing: read heads -> new_read_w output; write head 0 -> new_write_w output
    for (int h = 0; h < 4; h++)
        address_kernel<<<256, 256>>>(rp + (size_t)h*B_*PR_, PR_,
                                     dot + (size_t)h*B_*N_, nrm,
                                     prw + (size_t)h*B_*N_,
                                     o_rw + (size_t)h*B_*N_);
    address_kernel<<<256, 256>>>(wp, PW_, dot + (size_t)4*B_*N_, nrm, pww, o_ww);

    // Pass B: reads + head-0 update + dot for head 1
    passB_kernel<<<512, 256>>>(mem, o_mem, o_rw, o_ww, o_ro);

    // Write heads 1..3 (serial dependency through addressing)
    for (int h = 1; h < 4; h++) {
        address_kernel<<<256, 256>>>(wp + (size_t)h*B_*PW_, PW_,
                                     dot + (size_t)4*B_*N_, nrm,
                                     pww + (size_t)h*B_*N_,
                                     o_ww + (size_t)h*B_*N_);
        const float* knext = (h < 3) ? (wp + (size_t)(h+1)*B_*PW_) : nullptr;
        float* dnext = (h < 3) ? (dot + (size_t)4*B_*N_) : nullptr;
        pass_update_kernel<<<512, 256>>>(o_mem, o_ww + (size_t)h*B_*N_,
                                         wp + (size_t)h*B_*PW_, knext, dnext);
    }

    // Output GEMM: ntm_out = concat(ctrl, read_out) @ out_W + out_b
    concat_kernel<<<256, 256>>>(ctrl, 512, o_ro, 256, cin);
    sgemm_bias<<<dim3(4, 4), 256>>>(cin, outW, outb, out, 768, 256);
}

// round 2
// speedup vs baseline: 2.2631x; 2.2631x over previous
#include <cuda_runtime.h>
#include <math.h>

// Problem constants
constexpr int B_  = 256;
constexpr int N_  = 2048;
constexpr int M_  = 64;
constexpr int C_  = 512;
constexpr int PR_ = 70;   // M + 3 + SHIFT
constexpr int PW_ = 198;  // PR + 2M
constexpr float EPSF = 1e-8f;

// Output layout (floats): ntm_out, memory, read_out, new_read_w, new_write_w
constexpr size_t OUT_MEM = 65536;
constexpr size_t OUT_RO  = 33619968;
constexpr size_t OUT_RW  = 33685504;
constexpr size_t OUT_WW  = 35782656;

// ---------------- device scratch (no allocations allowed) ----------------
__device__ float g_ctrl[B_*C_];
__device__ float g_rp  [4*B_*PR_];
__device__ float g_wp  [4*B_*PW_];
__device__ float g_dot [5*(size_t)B_*N_];
__device__ float g_norm[(size_t)B_*N_];

__device__ __forceinline__ float softplusf(float x){ return x > 20.f ? x : log1pf(expf(x)); }
__device__ __forceinline__ float sigmoidf (float x){ return 1.f/(1.f+expf(-x)); }

__global__ void zero_kernel(float* __restrict__ p, int n)
{
    int i = blockIdx.x*blockDim.x + threadIdx.x;
    if (i < n) p[i] = 0.f;
}

// ---------------- GEMM body: out[256,Nc] = concat(A0,A1)[256,K] @ W[K,Nc] + bias ----------------
// Tile 32(M) x 64(N), K-step 32, 256 threads. blockIdx.x = col tile, blockIdx.y = row tile.
__device__ __forceinline__ void gemm_body(
    const float* __restrict__ A0, int ca,
    const float* __restrict__ A1, int cb,
    const float* __restrict__ W, const float* __restrict__ bias,
    float* __restrict__ out, int Nc)
{
    int col0 = blockIdx.x * 64;
    if (col0 >= Nc) return;
    int row0 = blockIdx.y * 32;
    int K = ca + cb;

    __shared__ float As[32][33];
    __shared__ float Ws[32][64];
    int tid = threadIdx.x;
    int tx = tid & 15, ty = tid >> 4;
    float acc[2][4] = {};

    for (int k0 = 0; k0 < K; k0 += 32) {
        // A tile: 32x32, each thread one float4
        {
            int m  = tid >> 3;
            int kk = (tid & 7) * 4;
            int r = row0 + m, c = k0 + kk;
            float4 v;
            if (c < ca) v = *(const float4*)(A0 + (size_t)r*ca + c);
            else        v = *(const float4*)(A1 + (size_t)r*cb + (c - ca));
            As[m][kk] = v.x; As[m][kk+1] = v.y; As[m][kk+2] = v.z; As[m][kk+3] = v.w;
        }
        // W tile: 32x64, each thread 8 elems
        {
            int kk = tid >> 3;
            int n0 = (tid & 7) * 8;
            const float* wrow = W + (size_t)(k0 + kk)*Nc + col0 + n0;
            #pragma unroll
            for (int j = 0; j < 8; j++) {
                int gn = col0 + n0 + j;
                Ws[kk][n0 + j] = (gn < Nc) ? wrow[j] : 0.f;
            }
        }
        __syncthreads();
        #pragma unroll
        for (int kk = 0; kk < 32; kk++) {
            float a0 = As[ty*2 + 0][kk];
            float a1 = As[ty*2 + 1][kk];
            float4 w4 = *(const float4*)&Ws[kk][tx*4];
            acc[0][0] += a0*w4.x; acc[0][1] += a0*w4.y; acc[0][2] += a0*w4.z; acc[0][3] += a0*w4.w;
            acc[1][0] += a1*w4.x; acc[1][1] += a1*w4.y; acc[1][2] += a1*w4.z; acc[1][3] += a1*w4.w;
        }
        __syncthreads();
    }
    #pragma unroll
    for (int i = 0; i < 2; i++) {
        int gm = row0 + ty*2 + i;
        #pragma unroll
        for (int j = 0; j < 4; j++) {
            int gn = col0 + tx*4 + j;
            if (gn < Nc) out[(size_t)gm*Nc + gn] = acc[i][j] + bias[gn];
        }
    }
}

__global__ void gemm_cat_kernel(const float* __restrict__ A0, int ca,
                                const float* __restrict__ A1, int cb,
                                const float* __restrict__ W, const float* __restrict__ bias,
                                float* __restrict__ out, int Nc)
{
    gemm_body(A0, ca, A1, cb, W, bias, out, Nc);
}

// All 8 head-parameter GEMMs in one launch: blockIdx.z = head (0..3 read, 4..7 write)
__global__ void gemm_heads_kernel(const float* __restrict__ ctrl,
                                  const float* __restrict__ readW, const float* __restrict__ readb,
                                  float* __restrict__ rp,
                                  const float* __restrict__ writeW, const float* __restrict__ writeb,
                                  float* __restrict__ wp)
{
    int h = blockIdx.z;
    const float *W, *bias; float* out; int Nc;
    if (h < 4) {
        W = readW + (size_t)h*C_*PR_; bias = readb + h*PR_;
        out = rp + (size_t)h*B_*PR_;  Nc = PR_;
    } else {
        int g = h - 4;
        W = writeW + (size_t)g*C_*PW_; bias = writeb + g*PW_;
        out = wp + (size_t)g*B_*PW_;   Nc = PW_;
    }
    gemm_body(ctrl, C_, nullptr, 0, W, bias, out, Nc);
}

// ---------------- Pass A: mem norms + 5 key dots (4 read heads + write head 0) ----------------
__global__ void passA_kernel(const float* __restrict__ mem)
{
    int bc = blockIdx.x; int b = bc >> 1; int nb = (bc & 1) << 10;
    int tid = threadIdx.x;
    int wid = tid >> 5, lane = tid & 31;
    int rsl = lane >> 3, mg = lane & 7;

    float kr[5][8];
    #pragma unroll
    for (int h = 0; h < 5; h++) {
        const float* kp = (h < 4) ? (g_rp + ((size_t)h*B_ + b)*PR_) : (g_wp + (size_t)b*PW_);
        #pragma unroll
        for (int j = 0; j < 8; j++) kr[h][j] = kp[mg*8 + j];
    }

    const float* base = mem + ((size_t)b*N_ + nb)*M_;
    for (int it = 0; it < 32; ++it) {
        int r = it*32 + wid*4 + rsl;
        const float4* rp4 = (const float4*)(base + (size_t)r*M_ + mg*8);
        float4 v0 = rp4[0], v1 = rp4[1];
        float vv[8] = {v0.x, v0.y, v0.z, v0.w, v1.x, v1.y, v1.z, v1.w};
        float nrm = 0.f;
        float d[5] = {0,0,0,0,0};
        #pragma unroll
        for (int j = 0; j < 8; j++) {
            nrm += vv[j]*vv[j];
            #pragma unroll
            for (int h = 0; h < 5; h++) d[h] += vv[j]*kr[h][j];
        }
        #pragma unroll
        for (int o = 1; o < 8; o <<= 1) {
            nrm += __shfl_xor_sync(0xffffffffu, nrm, o);
            #pragma unroll
            for (int h = 0; h < 5; h++) d[h] += __shfl_xor_sync(0xffffffffu, d[h], o);
        }
        if (mg == 0) {
            size_t ix = (size_t)b*N_ + nb + r;
            g_norm[ix] = sqrtf(nrm);
            #pragma unroll
            for (int h = 0; h < 5; h++) g_dot[(size_t)h*B_*N_ + ix] = d[h];
        }
    }
}

// ---------------- block reduction helpers (256 threads) ----------------
__device__ __forceinline__ float block_reduce_sum(float v, float* sbuf)
{
    int tid = threadIdx.x;
    #pragma unroll
    for (int o = 16; o > 0; o >>= 1) v += __shfl_xor_sync(0xffffffffu, v, o);
    if ((tid & 31) == 0) sbuf[tid >> 5] = v;
    __syncthreads();
    if (tid < 32) {
        float x = (tid < 8) ? sbuf[tid] : 0.f;
        #pragma unroll
        for (int o = 4; o > 0; o >>= 1) x += __shfl_xor_sync(0xffffffffu, x, o);
        if (tid == 0) sbuf[0] = x;
    }
    __syncthreads();
    float r = sbuf[0];
    __syncthreads();
    return r;
}

__device__ __forceinline__ float block_reduce_max(float v, float* sbuf)
{
    int tid = threadIdx.x;
    #pragma unroll
    for (int o = 16; o > 0; o >>= 1) v = fmaxf(v, __shfl_xor_sync(0xffffffffu, v, o));
    if ((tid & 31) == 0) sbuf[tid >> 5] = v;
    __syncthreads();
    if (tid < 32) {
        float x = (tid < 8) ? sbuf[tid] : -3.4e38f;
        #pragma unroll
        for (int o = 4; o > 0; o >>= 1) x = fmaxf(x, __shfl_xor_sync(0xffffffffu, x, o));
        if (tid == 0) sbuf[0] = x;
    }
    __syncthreads();
    float r = sbuf[0];
    __syncthreads();
    return r;
}

// ---------------- NTM addressing body ----------------
__device__ __forceinline__ void address_body(
    const float* __restrict__ p,          // param row for this (head,b)
    const float* __restrict__ dotb,       // [N]
    const float* __restrict__ nrmb,       // [N]
    const float* __restrict__ wpb,        // [N]
    float* __restrict__ woutb)            // [N]
{
    int tid = threadIdx.x;
    __shared__ float wg[2048];
    __shared__ float rbuf[32];
    __shared__ float sc[7];

    float kv = 0.f;
    if (tid < 64) { float x = p[tid]; kv = x*x; }
    float ksum = block_reduce_sum(kv, rbuf);
    if (tid == 0) {
        sc[0] = sqrtf(ksum);
        sc[1] = softplusf(p[64]);
        sc[2] = sigmoidf(p[65]);
        float a0 = p[66], a1 = p[67], a2 = p[68];
        float mx = fmaxf(a0, fmaxf(a1, a2));
        float e0 = expf(a0-mx), e1 = expf(a1-mx), e2 = expf(a2-mx);
        float es = e0 + e1 + e2;
        sc[3] = e0/es; sc[4] = e1/es; sc[5] = e2/es;
        sc[6] = 1.f + softplusf(p[69]);
    }
    __syncthreads();
    float knorm = sc[0], beta = sc[1], g = sc[2];
    float s0 = sc[3], s1 = sc[4], s2 = sc[5], gamma = sc[6];

    float x[8];
    float mx = -3.4e38f;
    #pragma unroll
    for (int i = 0; i < 8; i++) {
        int n = tid + i*256;
        float cosv = dotb[n] / (nrmb[n]*knorm + EPSF);
        x[i] = beta * cosv;
        mx = fmaxf(mx, x[i]);
    }
    float bmax = block_reduce_max(mx, rbuf);
    float lsum = 0.f;
    #pragma unroll
    for (int i = 0; i < 8; i++) {
        float e = expf(x[i] - bmax);
        wg[tid + i*256] = e;
        lsum += e;
    }
    float bsum = block_reduce_sum(lsum, rbuf);
    float inv = 1.f / bsum;
    #pragma unroll
    for (int i = 0; i < 8; i++) {
        int n = tid + i*256;
        wg[n] = g * (wg[n]*inv) + (1.f-g) * wpb[n];
    }
    __syncthreads();
    float wpow[8];
    lsum = 0.f;
    #pragma unroll
    for (int i = 0; i < 8; i++) {
        int n = tid + i*256;
        float ws = s0*wg[(n+1)&(N_-1)] + s1*wg[n] + s2*wg[(n-1)&(N_-1)];
        float t = powf(ws + EPSF, gamma);
        wpow[i] = t;
        lsum += t;
    }
    float psum = block_reduce_sum(lsum, rbuf);
    float ip = 1.f / psum;
    #pragma unroll
    for (int i = 0; i < 8; i++)
        woutb[tid + i*256] = wpow[i]*ip;
}

// Fused: 4 read heads + write head 0 (all independent). grid (B_, 5)
__global__ void address5_kernel(const float* __restrict__ prw,
                                const float* __restrict__ pww,
                                float* __restrict__ o_rw,
                                float* __restrict__ o_ww)
{
    int b = blockIdx.x, h = blockIdx.y;
    const float *p, *dotp, *wprev; float* wout;
    if (h < 4) {
        p     = g_rp + ((size_t)h*B_ + b)*PR_;
        dotp  = g_dot + (size_t)h*B_*N_ + (size_t)b*N_;
        wprev = prw  + (size_t)h*B_*N_ + (size_t)b*N_;
        wout  = o_rw + (size_t)h*B_*N_ + (size_t)b*N_;
    } else {
        p     = g_wp + (size_t)b*PW_;
        dotp  = g_dot + (size_t)4*B_*N_ + (size_t)b*N_;
        wprev = pww  + (size_t)b*N_;
        wout  = o_ww + (size_t)b*N_;
    }
    address_body(p, dotp, g_norm + (size_t)b*N_, wprev, wout);
}

// Single write head h (1..3). grid (B_)
__global__ void address1_kernel(int h,
                                const float* __restrict__ pww,
                                float* __restrict__ o_ww)
{
    int b = blockIdx.x;
    address_body(g_wp + ((size_t)h*B_ + b)*PW_,
                 g_dot + (size_t)4*B_*N_ + (size_t)b*N_,
                 g_norm + (size_t)b*N_,
                 pww  + (size_t)h*B_*N_ + (size_t)b*N_,
                 o_ww + (size_t)h*B_*N_ + (size_t)b*N_);
}

// ---------------- Pass B: reads einsum + head0 update + dot for head1 ----------------
__global__ void passB_kernel(const float* __restrict__ mem_in, float* __restrict__ mem_out,
                             const float* __restrict__ wr,
                             const float* __restrict__ ww0,
                             float* __restrict__ read_out)
{
    int bc = blockIdx.x; int b = bc >> 1; int nb = (bc & 1) << 10;
    int tid = threadIdx.x, wid = tid >> 5, lane = tid & 31;

    __shared__ float sE[64], sA[64];
    __shared__ float2 sred[8][4][32];
    if (tid < 64) {
        const float* pwb = g_wp + (size_t)b*PW_;
        sE[tid] = sigmoidf(pwb[70 + tid]);
        sA[tid] = tanhf(pwb[134 + tid]);
    }
    const float* k1p = g_wp + ((size_t)1*B_ + b)*PW_;
    float kx = k1p[2*lane], ky = k1p[2*lane + 1];
    __syncthreads();
    float ex = sE[2*lane], ey = sE[2*lane+1];
    float ax = sA[2*lane], ay = sA[2*lane+1];

    float2 acc[4] = {{0,0},{0,0},{0,0},{0,0}};
    float* dot1 = g_dot + (size_t)4*B_*N_;

    for (int it = 0; it < 128; ++it) {
        int n = nb + it*8 + wid;
        size_t wix = (size_t)b*N_ + n;
        size_t off = wix*M_ + 2*lane;
        float2 v = *(const float2*)(mem_in + off);
        float w0 = ww0[wix];
        #pragma unroll
        for (int h = 0; h < 4; h++) {
            float wv = wr[(size_t)h*B_*N_ + wix];
            acc[h].x += wv*v.x; acc[h].y += wv*v.y;
        }
        float2 u;
        u.x = v.x*(1.f - w0*ex) + w0*ax;
        u.y = v.y*(1.f - w0*ey) + w0*ay;
        *(float2*)(mem_out + off) = u;
        float d  = u.x*kx + u.y*ky;
        float nm = u.x*u.x + u.y*u.y;
        #pragma unroll
        for (int o = 16; o > 0; o >>= 1) {
            d  += __shfl_xor_sync(0xffffffffu, d, o);
            nm += __shfl_xor_sync(0xffffffffu, nm, o);
        }
        if (lane == 0) { dot1[wix] = d; g_norm[wix] = sqrtf(nm); }
    }

    #pragma unroll
    for (int h = 0; h < 4; h++) sred[wid][h][lane] = acc[h];
    __syncthreads();
    int h = tid >> 6, l = (tid >> 1) & 31, c = tid & 1;
    float s = 0.f;
    #pragma unroll
    for (int w = 0; w < 8; w++) {
        float2 t = sred[w][h][l];
        s += c ? t.y : t.x;
    }
    atomicAdd(read_out + (size_t)b*256 + h*64 + 2*l + c, s);
}

// ---------------- Pass C/D/E: in-place memory update (+ optional next-head dot) ----------------
__global__ void pass_update_kernel(float* __restrict__ memio,
                                   const float* __restrict__ ww,
                                   const float* __restrict__ pw_head,
                                   const float* __restrict__ knext,
                                   float* __restrict__ dot_out)
{
    int bc = blockIdx.x; int b = bc >> 1; int nb = (bc & 1) << 10;
    int tid = threadIdx.x, wid = tid >> 5, lane = tid & 31;

    __shared__ float sE[64], sA[64];
    if (tid < 64) {
        const float* pwb = pw_head + (size_t)b*PW_;
        sE[tid] = sigmoidf(pwb[70 + tid]);
        sA[tid] = tanhf(pwb[134 + tid]);
    }
    float kx = 0.f, ky = 0.f;
    bool do_dot = (knext != nullptr);
    if (do_dot) {
        const float* kb = knext + (size_t)b*PW_;
        kx = kb[2*lane]; ky = kb[2*lane + 1];
    }
    __syncthreads();
    float ex = sE[2*lane], ey = sE[2*lane+1];
    float ax = sA[2*lane], ay = sA[2*lane+1];

    for (int it = 0; it < 128; ++it) {
        int n = nb + it*8 + wid;
        size_t wix = (size_t)b*N_ + n;
        size_t off = wix*M_ + 2*lane;
        float2 v = *(const float2*)(memio + off);
        float w0 = ww[wix];
        float2 u;
        u.x = v.x*(1.f - w0*ex) + w0*ax;
        u.y = v.y*(1.f - w0*ey) + w0*ay;
        *(float2*)(memio + off) = u;
        if (do_dot) {
            float d  = u.x*kx + u.y*ky;
            float nm = u.x*u.x + u.y*u.y;
            #pragma unroll
            for (int o = 16; o > 0; o >>= 1) {
                d  += __shfl_xor_sync(0xffffffffu, d, o);
                nm += __shfl_xor_sync(0xffffffffu, nm, o);
            }
            if (lane == 0) { dot_out[wix] = d; g_norm[wix] = sqrtf(nm); }
        }
    }
}

// ---------------- host launcher ----------------
extern "C" void kernel_launch(void* const* d_in, const int* in_sizes, int n_in,
                              void* d_out, int out_size)
{
    const float* ext    = (const float*)d_in[0];
    const float* pread  = (const float*)d_in[1];
    const float* prw    = (const float*)d_in[2];
    const float* pww    = (const float*)d_in[3];
    const float* mem    = (const float*)d_in[4];
    const float* ctrlW  = (const float*)d_in[5];
    const float* ctrlb  = (const float*)d_in[6];
    const float* readW  = (const float*)d_in[7];
    const float* readb  = (const float*)d_in[8];
    const float* writeW = (const float*)d_in[9];
    const float* writeb = (const float*)d_in[10];
    const float* outW   = (const float*)d_in[11];
    const float* outb   = (const float*)d_in[12];
    float* out = (float*)d_out;

    float *ctrl, *rp, *wp, *dot;
    cudaGetSymbolAddress((void**)&ctrl, g_ctrl);
    cudaGetSymbolAddress((void**)&rp,   g_rp);
    cudaGetSymbolAddress((void**)&wp,   g_wp);
    cudaGetSymbolAddress((void**)&dot,  g_dot);

    float* o_mem = out + OUT_MEM;
    float* o_ro  = out + OUT_RO;
    float* o_rw  = out + OUT_RW;
    float* o_ww  = out + OUT_WW;

    // Controller GEMM with fused concat: [ext | pread] @ ctrlW + b -> ctrl [256,512]
    gemm_cat_kernel<<<dim3(8, 8), 256>>>(ext, 256, pread, 256, ctrlW, ctrlb, ctrl, 512);

    // All 8 head parameter GEMMs in one launch
    gemm_heads_kernel<<<dim3(4, 8, 8), 256>>>(ctrl, readW, readb, rp, writeW, writeb, wp);

    // Pass A: norms + cos dots for 4 read heads + write head 0
    passA_kernel<<<512, 256>>>(mem);

    zero_kernel<<<256, 256>>>(o_ro, B_*256);

    // Addressing for 4 read heads + write head 0 (fused)
    address5_kernel<<<dim3(256, 5), 256>>>(prw, pww, o_rw, o_ww);

    // Pass B: reads + head-0 update + dot/norm for head 1
    passB_kernel<<<512, 256>>>(mem, o_mem, o_rw, o_ww, o_ro);

    // Write heads 1..3 (serial through addressing)
    for (int h = 1; h < 4; h++) {
        address1_kernel<<<256, 256>>>(h, pww, o_ww);
        const float* knext = (h < 3) ? (wp + (size_t)(h+1)*B_*PW_) : nullptr;
        float* dnext = (h < 3) ? (dot + (size_t)4*B_*N_) : nullptr;
        pass_update_kernel<<<512, 256>>>(o_mem, o_ww + (size_t)h*B_*N_,
                                         wp + (size_t)h*B_*PW_, knext, dnext);
    }

    // Output GEMM with fused concat: [ctrl | read_out] @ out_W + out_b
    gemm_cat_kernel<<<dim3(4, 8), 256>>>(ctrl, 512, o_ro, 256, outW, outb, out, 256);
}

// round 4
// speedup vs baseline: 3.1914x; 1.4102x over previous
#include <cuda_runtime.h>
#include <math.h>

// Problem constants
constexpr int B_  = 256;
constexpr int N_  = 2048;
constexpr int M_  = 64;
constexpr int C_  = 512;
constexpr int PR_ = 70;   // M + 3 + SHIFT
constexpr int PW_ = 198;  // PR + 2M
constexpr float EPSF = 1e-8f;

// Output layout (floats): ntm_out, memory, read_out, new_read_w, new_write_w
constexpr size_t OUT_MEM = 65536;
constexpr size_t OUT_RO  = 33619968;
constexpr size_t OUT_RW  = 33685504;
constexpr size_t OUT_WW  = 35782656;

// ---------------- device scratch (no allocations allowed) ----------------
__device__ float g_ctrl[B_*C_];
__device__ float g_rp  [4*B_*PR_];
__device__ float g_wp  [4*B_*PW_];
__device__ float g_dot [5*(size_t)B_*N_];
__device__ float g_norm[(size_t)B_*N_];
__device__ float g_ropart[2*B_*256];

__device__ __forceinline__ float softplusf(float x){ return x > 20.f ? x : log1pf(expf(x)); }
__device__ __forceinline__ float sigmoidf (float x){ return 1.f/(1.f+expf(-x)); }

// ---------------- GEMM body: out[256,Nc] = concat(A0,A1)[256,K] @ W[K,Nc] + bias ----------------
__device__ __forceinline__ void gemm_body(
    const float* __restrict__ A0, int ca,
    const float* __restrict__ A1, int cb,
    const float* __restrict__ W, const float* __restrict__ bias,
    float* __restrict__ out, int Nc)
{
    int col0 = blockIdx.x * 64;
    if (col0 >= Nc) return;
    int row0 = blockIdx.y * 32;
    int K = ca + cb;

    __shared__ float As[32][33];
    __shared__ float Ws[32][64];
    int tid = threadIdx.x;
    int tx = tid & 15, ty = tid >> 4;
    float acc[2][4] = {};

    for (int k0 = 0; k0 < K; k0 += 32) {
        {
            int m  = tid >> 3;
            int kk = (tid & 7) * 4;
            int r = row0 + m, c = k0 + kk;
            float4 v;
            if (c < ca) v = *(const float4*)(A0 + (size_t)r*ca + c);
            else        v = *(const float4*)(A1 + (size_t)r*cb + (c - ca));
            As[m][kk] = v.x; As[m][kk+1] = v.y; As[m][kk+2] = v.z; As[m][kk+3] = v.w;
        }
        {
            int kk = tid >> 3;
            int n0 = (tid & 7) * 8;
            const float* wrow = W + (size_t)(k0 + kk)*Nc + col0 + n0;
            #pragma unroll
            for (int j = 0; j < 8; j++) {
                int gn = col0 + n0 + j;
                Ws[kk][n0 + j] = (gn < Nc) ? wrow[j] : 0.f;
            }
        }
        __syncthreads();
        #pragma unroll
        for (int kk = 0; kk < 32; kk++) {
            float a0 = As[ty*2 + 0][kk];
            float a1 = As[ty*2 + 1][kk];
            float4 w4 = *(const float4*)&Ws[kk][tx*4];
            acc[0][0] += a0*w4.x; acc[0][1] += a0*w4.y; acc[0][2] += a0*w4.z; acc[0][3] += a0*w4.w;
            acc[1][0] += a1*w4.x; acc[1][1] += a1*w4.y; acc[1][2] += a1*w4.z; acc[1][3] += a1*w4.w;
        }
        __syncthreads();
    }
    #pragma unroll
    for (int i = 0; i < 2; i++) {
        int gm = row0 + ty*2 + i;
        #pragma unroll
        for (int j = 0; j < 4; j++) {
            int gn = col0 + tx*4 + j;
            if (gn < Nc) out[(size_t)gm*Nc + gn] = acc[i][j] + bias[gn];
        }
    }
}

__global__ void gemm_cat_kernel(const float* __restrict__ A0, int ca,
                                const float* __restrict__ A1, int cb,
                                const float* __restrict__ W, const float* __restrict__ bias,
                                float* __restrict__ out, int Nc)
{
    gemm_body(A0, ca, A1, cb, W, bias, out, Nc);
}

__global__ void gemm_heads_kernel(const float* __restrict__ ctrl,
                                  const float* __restrict__ readW, const float* __restrict__ readb,
                                  float* __restrict__ rp,
                                  const float* __restrict__ writeW, const float* __restrict__ writeb,
                                  float* __restrict__ wp)
{
    int h = blockIdx.z;
    const float *W, *bias; float* out; int Nc;
    if (h < 4) {
        W = readW + (size_t)h*C_*PR_; bias = readb + h*PR_;
        out = rp + (size_t)h*B_*PR_;  Nc = PR_;
    } else {
        int g = h - 4;
        W = writeW + (size_t)g*C_*PW_; bias = writeb + g*PW_;
        out = wp + (size_t)g*B_*PW_;   Nc = PW_;
    }
    gemm_body(ctrl, C_, nullptr, 0, W, bias, out, Nc);
}

// ---------------- Pass A: mem norms + 5 key dots ----------------
// Half-warp (16 lanes, float4/lane) per row; 2-row unroll -> 4 independent float4 loads.
__global__ void __launch_bounds__(256) passA_kernel(const float* __restrict__ mem)
{
    int bc = blockIdx.x; int b = bc >> 1; int nb = (bc & 1) << 10;
    int tid = threadIdx.x, wid = tid >> 5, lane = tid & 31;
    int hw = lane >> 4, l16 = lane & 15;

    // Scalar key loads (key rows are NOT 16B aligned: PR_=70, PW_=198)
    float4 kr[5];
    #pragma unroll
    for (int h = 0; h < 5; h++) {
        const float* kp = (h < 4) ? (g_rp + ((size_t)h*B_ + b)*PR_) : (g_wp + (size_t)b*PW_);
        kr[h].x = kp[l16*4 + 0];
        kr[h].y = kp[l16*4 + 1];
        kr[h].z = kp[l16*4 + 2];
        kr[h].w = kp[l16*4 + 3];
    }

    const float* base = mem + ((size_t)b*N_ + nb)*M_;
    for (int it = 0; it < 64; it += 2) {
        int rA = it*16 + wid*2 + hw;
        int rB = rA + 16;
        float4 va = *(const float4*)(base + (size_t)rA*M_ + l16*4);
        float4 vb = *(const float4*)(base + (size_t)rB*M_ + l16*4);

        float nA = va.x*va.x + va.y*va.y + va.z*va.z + va.w*va.w;
        float nB = vb.x*vb.x + vb.y*vb.y + vb.z*vb.z + vb.w*vb.w;
        float dA[5], dB[5];
        #pragma unroll
        for (int h = 0; h < 5; h++) {
            dA[h] = va.x*kr[h].x + va.y*kr[h].y + va.z*kr[h].z + va.w*kr[h].w;
            dB[h] = vb.x*kr[h].x + vb.y*kr[h].y + vb.z*kr[h].z + vb.w*kr[h].w;
        }
        #pragma unroll
        for (int o = 8; o > 0; o >>= 1) {
            nA += __shfl_xor_sync(0xffffffffu, nA, o);
            nB += __shfl_xor_sync(0xffffffffu, nB, o);
            #pragma unroll
            for (int h = 0; h < 5; h++) {
                dA[h] += __shfl_xor_sync(0xffffffffu, dA[h], o);
                dB[h] += __shfl_xor_sync(0xffffffffu, dB[h], o);
            }
        }
        if (l16 == 0) {
            size_t ixA = (size_t)b*N_ + nb + rA;
            size_t ixB = (size_t)b*N_ + nb + rB;
            g_norm[ixA] = sqrtf(nA);
            g_norm[ixB] = sqrtf(nB);
            #pragma unroll
            for (int h = 0; h < 5; h++) {
                g_dot[(size_t)h*B_*N_ + ixA] = dA[h];
                g_dot[(size_t)h*B_*N_ + ixB] = dB[h];
            }
        }
    }
}

// ---------------- block reduction helpers (256 threads) ----------------
__device__ __forceinline__ float block_reduce_sum(float v, float* sbuf)
{
    int tid = threadIdx.x;
    #pragma unroll
    for (int o = 16; o > 0; o >>= 1) v += __shfl_xor_sync(0xffffffffu, v, o);
    if ((tid & 31) == 0) sbuf[tid >> 5] = v;
    __syncthreads();
    if (tid < 32) {
        float x = (tid < 8) ? sbuf[tid] : 0.f;
        #pragma unroll
        for (int o = 4; o > 0; o >>= 1) x += __shfl_xor_sync(0xffffffffu, x, o);
        if (tid == 0) sbuf[0] = x;
    }
    __syncthreads();
    float r = sbuf[0];
    __syncthreads();
    return r;
}

__device__ __forceinline__ float block_reduce_max(float v, float* sbuf)
{
    int tid = threadIdx.x;
    #pragma unroll
    for (int o = 16; o > 0; o >>= 1) v = fmaxf(v, __shfl_xor_sync(0xffffffffu, v, o));
    if ((tid & 31) == 0) sbuf[tid >> 5] = v;
    __syncthreads();
    if (tid < 32) {
        float x = (tid < 8) ? sbuf[tid] : -3.4e38f;
        #pragma unroll
        for (int o = 4; o > 0; o >>= 1) x = fmaxf(x, __shfl_xor_sync(0xffffffffu, x, o));
        if (tid == 0) sbuf[0] = x;
    }
    __syncthreads();
    float r = sbuf[0];
    __syncthreads();
    return r;
}

// ---------------- NTM addressing body ----------------
__device__ __forceinline__ void address_body(
    const float* __restrict__ p,
    const float* __restrict__ dotb,
    const float* __restrict__ nrmb,
    const float* __restrict__ wpb,
    float* __restrict__ woutb)
{
    int tid = threadIdx.x;
    __shared__ float wg[2048];
    __shared__ float rbuf[32];
    __shared__ float sc[7];

    float kv = 0.f;
    if (tid < 64) { float x = p[tid]; kv = x*x; }
    float ksum = block_reduce_sum(kv, rbuf);
    if (tid == 0) {
        sc[0] = sqrtf(ksum);
        sc[1] = softplusf(p[64]);
        sc[2] = sigmoidf(p[65]);
        float a0 = p[66], a1 = p[67], a2 = p[68];
        float mx = fmaxf(a0, fmaxf(a1, a2));
        float e0 = expf(a0-mx), e1 = expf(a1-mx), e2 = expf(a2-mx);
        float es = e0 + e1 + e2;
        sc[3] = e0/es; sc[4] = e1/es; sc[5] = e2/es;
        sc[6] = 1.f + softplusf(p[69]);
    }
    __syncthreads();
    float knorm = sc[0], beta = sc[1], g = sc[2];
    float s0 = sc[3], s1 = sc[4], s2 = sc[5], gamma = sc[6];

    float x[8];
    float mx = -3.4e38f;
    #pragma unroll
    for (int i = 0; i < 8; i++) {
        int n = tid + i*256;
        float cosv = dotb[n] / (nrmb[n]*knorm + EPSF);
        x[i] = beta * cosv;
        mx = fmaxf(mx, x[i]);
    }
    float bmax = block_reduce_max(mx, rbuf);
    float lsum = 0.f;
    #pragma unroll
    for (int i = 0; i < 8; i++) {
        float e = __expf(x[i] - bmax);
        wg[tid + i*256] = e;
        lsum += e;
    }
    float bsum = block_reduce_sum(lsum, rbuf);
    float inv = 1.f / bsum;
    #pragma unroll
    for (int i = 0; i < 8; i++) {
        int n = tid + i*256;
        wg[n] = g * (wg[n]*inv) + (1.f-g) * wpb[n];
    }
    __syncthreads();
    float wpow[8];
    lsum = 0.f;
    #pragma unroll
    for (int i = 0; i < 8; i++) {
        int n = tid + i*256;
        float ws = s0*wg[(n+1)&(N_-1)] + s1*wg[n] + s2*wg[(n-1)&(N_-1)];
        float t = __powf(ws + EPSF, gamma);
        wpow[i] = t;
        lsum += t;
    }
    float psum = block_reduce_sum(lsum, rbuf);
    float ip = 1.f / psum;
    #pragma unroll
    for (int i = 0; i < 8; i++)
        woutb[tid + i*256] = wpow[i]*ip;
}

__global__ void address5_kernel(const float* __restrict__ prw,
                                const float* __restrict__ pww,
                                float* __restrict__ o_rw,
                                float* __restrict__ o_ww)
{
    int b = blockIdx.x, h = blockIdx.y;
    const float *p, *dotp, *wprev; float* wout;
    if (h < 4) {
        p     = g_rp + ((size_t)h*B_ + b)*PR_;
        dotp  = g_dot + (size_t)h*B_*N_ + (size_t)b*N_;
        wprev = prw  + (size_t)h*B_*N_ + (size_t)b*N_;
        wout  = o_rw + (size_t)h*B_*N_ + (size_t)b*N_;
    } else {
        p     = g_wp + (size_t)b*PW_;
        dotp  = g_dot + (size_t)4*B_*N_ + (size_t)b*N_;
        wprev = pww  + (size_t)b*N_;
        wout  = o_ww + (size_t)b*N_;
    }
    address_body(p, dotp, g_norm + (size_t)b*N_, wprev, wout);
}

__global__ void address1_kernel(int h,
                                const float* __restrict__ pww,
                                float* __restrict__ o_ww)
{
    int b = blockIdx.x;
    address_body(g_wp + ((size_t)h*B_ + b)*PW_,
                 g_dot + (size_t)4*B_*N_ + (size_t)b*N_,
                 g_norm + (size_t)b*N_,
                 pww  + (size_t)h*B_*N_ + (size_t)b*N_,
                 o_ww + (size_t)h*B_*N_ + (size_t)b*N_);
}

// ---------------- Pass B: reads einsum + head0 update + dot for head1 ----------------
// 4 rows per warp-iteration, loads front-batched (MLP>=4).
__global__ void __launch_bounds__(256) passB_kernel(
    const float* __restrict__ mem_in, float* __restrict__ mem_out,
    const float* __restrict__ wr,
    const float* __restrict__ ww0,
    float* __restrict__ ro_part)
{
    int bc = blockIdx.x; int b = bc >> 1; int nb = (bc & 1) << 10;
    int tid = threadIdx.x, wid = tid >> 5, lane = tid & 31;

    __shared__ float sE[64], sA[64];
    __shared__ float2 sred[8][4][32];
    if (tid < 64) {
        const float* pwb = g_wp + (size_t)b*PW_;
        sE[tid] = sigmoidf(pwb[70 + tid]);
        sA[tid] = tanhf(pwb[134 + tid]);
    }
    const float* k1p = g_wp + ((size_t)1*B_ + b)*PW_;
    float kx = k1p[2*lane], ky = k1p[2*lane + 1];
    __syncthreads();
    float ex = sE[2*lane], ey = sE[2*lane+1];
    float ax = sA[2*lane], ay = sA[2*lane+1];

    float2 acc[4] = {{0,0},{0,0},{0,0},{0,0}};
    float* dot1 = g_dot + (size_t)4*B_*N_;

    for (int it = 0; it < 32; ++it) {
        size_t wix0 = (size_t)b*N_ + nb + it*32 + wid*4;
        const float* src = mem_in + wix0*M_ + 2*lane;

        float2 v[4];
        v[0] = *(const float2*)(src);
        v[1] = *(const float2*)(src + M_);
        v[2] = *(const float2*)(src + 2*M_);
        v[3] = *(const float2*)(src + 3*M_);
        float w0[4];
        #pragma unroll
        for (int r = 0; r < 4; r++) w0[r] = ww0[wix0 + r];
        float wv[4][4];
        #pragma unroll
        for (int h = 0; h < 4; h++) {
            const float* wh = wr + (size_t)h*B_*N_ + wix0;
            wv[h][0] = wh[0]; wv[h][1] = wh[1]; wv[h][2] = wh[2]; wv[h][3] = wh[3];
        }

        #pragma unroll
        for (int h = 0; h < 4; h++) {
            #pragma unroll
            for (int r = 0; r < 4; r++) {
                acc[h].x += wv[h][r]*v[r].x;
                acc[h].y += wv[h][r]*v[r].y;
            }
        }

        float d[4], nm[4];
        float* dst = mem_out + wix0*M_ + 2*lane;
        #pragma unroll
        for (int r = 0; r < 4; r++) {
            float2 u;
            u.x = v[r].x*(1.f - w0[r]*ex) + w0[r]*ax;
            u.y = v[r].y*(1.f - w0[r]*ey) + w0[r]*ay;
            *(float2*)(dst + (size_t)r*M_) = u;
            d[r]  = u.x*kx + u.y*ky;
            nm[r] = u.x*u.x + u.y*u.y;
        }
        #pragma unroll
        for (int o = 16; o > 0; o >>= 1) {
            #pragma unroll
            for (int r = 0; r < 4; r++) {
                d[r]  += __shfl_xor_sync(0xffffffffu, d[r], o);
                nm[r] += __shfl_xor_sync(0xffffffffu, nm[r], o);
            }
        }
        if (lane == 0) {
            #pragma unroll
            for (int r = 0; r < 4; r++) {
                dot1[wix0 + r]   = d[r];
                g_norm[wix0 + r] = sqrtf(nm[r]);
            }
        }
    }

    #pragma unroll
    for (int h = 0; h < 4; h++) sred[wid][h][lane] = acc[h];
    __syncthreads();
    int h = tid >> 6, l = (tid >> 1) & 31, c = tid & 1;
    float s = 0.f;
    #pragma unroll
    for (int w = 0; w < 8; w++) {
        float2 t = sred[w][h][l];
        s += c ? t.y : t.x;
    }
    ro_part[(size_t)(bc & 1)*B_*256 + (size_t)b*256 + h*64 + 2*l + c] = s;
}

__global__ void sum_ro_kernel(const float* __restrict__ part, float* __restrict__ o_ro)
{
    int i = blockIdx.x*blockDim.x + threadIdx.x;
    o_ro[i] = part[i] + part[B_*256 + i];
}

// ---------------- Pass C/D/E: in-place memory update (+ optional next-head dot) ----------------
__global__ void __launch_bounds__(256) pass_update_kernel(
    float* __restrict__ memio,
    const float* __restrict__ ww,
    const float* __restrict__ pw_head,
    const float* __restrict__ knext,
    float* __restrict__ dot_out)
{
    int bc = blockIdx.x; int b = bc >> 1; int nb = (bc & 1) << 10;
    int tid = threadIdx.x, wid = tid >> 5, lane = tid & 31;

    __shared__ float sE[64], sA[64];
    if (tid < 64) {
        const float* pwb = pw_head + (size_t)b*PW_;
        sE[tid] = sigmoidf(pwb[70 + tid]);
        sA[tid] = tanhf(pwb[134 + tid]);
    }
    float kx = 0.f, ky = 0.f;
    bool do_dot = (knext != nullptr);
    if (do_dot) {
        const float* kb = knext + (size_t)b*PW_;
        kx = kb[2*lane]; ky = kb[2*lane + 1];
    }
    __syncthreads();
    float ex = sE[2*lane], ey = sE[2*lane+1];
    float ax = sA[2*lane], ay = sA[2*lane+1];

    for (int it = 0; it < 32; ++it) {
        size_t wix0 = (size_t)b*N_ + nb + it*32 + wid*4;
        float* base = memio + wix0*M_ + 2*lane;

        float2 v[4];
        v[0] = *(const float2*)(base);
        v[1] = *(const float2*)(base + M_);
        v[2] = *(const float2*)(base + 2*M_);
        v[3] = *(const float2*)(base + 3*M_);
        float w0[4];
        #pragma unroll
        for (int r = 0; r < 4; r++) w0[r] = ww[wix0 + r];

        float2 u[4];
        #pragma unroll
        for (int r = 0; r < 4; r++) {
            u[r].x = v[r].x*(1.f - w0[r]*ex) + w0[r]*ax;
            u[r].y = v[r].y*(1.f - w0[r]*ey) + w0[r]*ay;
            *(float2*)(base + (size_t)r*M_) = u[r];
        }
        if (do_dot) {
            float d[4], nm[4];
            #pragma unroll
            for (int r = 0; r < 4; r++) {
                d[r]  = u[r].x*kx + u[r].y*ky;
                nm[r] = u[r].x*u[r].x + u[r].y*u[r].y;
            }
            #pragma unroll
            for (int o = 16; o > 0; o >>= 1) {
                #pragma unroll
                for (int r = 0; r < 4; r++) {
                    d[r]  += __shfl_xor_sync(0xffffffffu, d[r], o);
                    nm[r] += __shfl_xor_sync(0xffffffffu, nm[r], o);
                }
            }
            if (lane == 0) {
                #pragma unroll
                for (int r = 0; r < 4; r++) {
                    dot_out[wix0 + r] = d[r];
                    g_norm[wix0 + r]  = sqrtf(nm[r]);
                }
            }
        }
    }
}

// ---------------- host launcher ----------------
extern "C" void kernel_launch(void* const* d_in, const int* in_sizes, int n_in,
                              void* d_out, int out_size)
{
    const float* ext    = (const float*)d_in[0];
    const float* pread  = (const float*)d_in[1];
    const float* prw    = (const float*)d_in[2];
    const float* pww    = (const float*)d_in[3];
    const float* mem    = (const float*)d_in[4];
    const float* ctrlW  = (const float*)d_in[5];
    const float* ctrlb  = (const float*)d_in[6];
    const float* readW  = (const float*)d_in[7];
    const float* readb  = (const float*)d_in[8];
    const float* writeW = (const float*)d_in[9];
    const float* writeb = (const float*)d_in[10];
    const float* outW   = (const float*)d_in[11];
    const float* outb   = (const float*)d_in[12];
    float* out = (float*)d_out;

    float *ctrl, *rp, *wp, *dot, *ropart;
    cudaGetSymbolAddress((void**)&ctrl,   g_ctrl);
    cudaGetSymbolAddress((void**)&rp,     g_rp);
    cudaGetSymbolAddress((void**)&wp,     g_wp);
    cudaGetSymbolAddress((void**)&dot,    g_dot);
    cudaGetSymbolAddress((void**)&ropart, g_ropart);

    float* o_mem = out + OUT_MEM;
    float* o_ro  = out + OUT_RO;
    float* o_rw  = out + OUT_RW;
    float* o_ww  = out + OUT_WW;

    // Controller GEMM with fused concat
    gemm_cat_kernel<<<dim3(8, 8), 256>>>(ext, 256, pread, 256, ctrlW, ctrlb, ctrl, 512);

    // All 8 head parameter GEMMs in one launch
    gemm_heads_kernel<<<dim3(4, 8, 8), 256>>>(ctrl, readW, readb, rp, writeW, writeb, wp);

    // Pass A: norms + cos dots for 4 read heads + write head 0
    passA_kernel<<<512, 256>>>(mem);

    // Addressing for 4 read heads + write head 0 (fused)
    address5_kernel<<<dim3(256, 5), 256>>>(prw, pww, o_rw, o_ww);

    // Pass B: reads + head-0 update + dot/norm for head 1
    passB_kernel<<<512, 256>>>(mem, o_mem, o_rw, o_ww, ropart);

    // read_out = sum of the two half-N partials
    sum_ro_kernel<<<64, 1024>>>(ropart, o_ro);

    // Write heads 1..3 (serial through addressing)
    for (int h = 1; h < 4; h++) {
        address1_kernel<<<256, 256>>>(h, pww, o_ww);
        const float* knext = (h < 3) ? (wp + (size_t)(h+1)*B_*PW_) : nullptr;
        float* dnext = (h < 3) ? (dot + (size_t)4*B_*N_) : nullptr;
        pass_update_kernel<<<512, 256>>>(o_mem, o_ww + (size_t)h*B_*N_,
                                         wp + (size_t)h*B_*PW_, knext, dnext);
    }

    // Output GEMM with fused concat
    gemm_cat_kernel<<<dim3(4, 8), 256>>>(ctrl, 512, o_ro, 256, outW, outb, out, 256);
}

// round 5
// speedup vs baseline: 3.3734x; 1.0570x over previous
#include <cuda_runtime.h>
#include <math.h>

// Problem constants
constexpr int B_  = 256;
constexpr int N_  = 2048;
constexpr int M_  = 64;
constexpr int C_  = 512;
constexpr int PR_ = 70;   // M + 3 + SHIFT
constexpr int PW_ = 198;  // PR + 2M
constexpr float EPSF = 1e-8f;

// Output layout (floats): ntm_out, memory, read_out, new_read_w, new_write_w
constexpr size_t OUT_MEM = 65536;
constexpr size_t OUT_RO  = 33619968;
constexpr size_t OUT_RW  = 33685504;
constexpr size_t OUT_WW  = 35782656;

// ---------------- device scratch (no allocations allowed) ----------------
__device__ float g_ctrl[B_*C_];
__device__ float g_rp  [4*B_*PR_];
__device__ float g_wp  [4*B_*PW_];
__device__ float g_dot [5*(size_t)B_*N_];
__device__ float g_norm[(size_t)B_*N_];
__device__ float g_base[6*(size_t)B_*N_];   // base dots: Da,Db,S1,S2,T0,T1
__device__ float g_ropart[2*B_*256];

__device__ __forceinline__ float softplusf(float x){ return x > 20.f ? x : log1pf(expf(x)); }
__device__ __forceinline__ float sigmoidf (float x){ return 1.f/(1.f+expf(-x)); }

// ---------------- GEMM body: out[256,Nc] = concat(A0,A1)[256,K] @ W[K,Nc] + bias ----------------
__device__ __forceinline__ void gemm_body(
    const float* __restrict__ A0, int ca,
    const float* __restrict__ A1, int cb,
    const float* __restrict__ W, const float* __restrict__ bias,
    float* __restrict__ out, int Nc)
{
    int col0 = blockIdx.x * 64;
    if (col0 >= Nc) return;
    int row0 = blockIdx.y * 32;
    int K = ca + cb;

    __shared__ float As[32][33];
    __shared__ float Ws[32][64];
    int tid = threadIdx.x;
    int tx = tid & 15, ty = tid >> 4;
    float acc[2][4] = {};

    for (int k0 = 0; k0 < K; k0 += 32) {
        {
            int m  = tid >> 3;
            int kk = (tid & 7) * 4;
            int r = row0 + m, c = k0 + kk;
            float4 v;
            if (c < ca) v = *(const float4*)(A0 + (size_t)r*ca + c);
            else        v = *(const float4*)(A1 + (size_t)r*cb + (c - ca));
            As[m][kk] = v.x; As[m][kk+1] = v.y; As[m][kk+2] = v.z; As[m][kk+3] = v.w;
        }
        {
            int kk = tid >> 3;
            int n0 = (tid & 7) * 8;
            const float* wrow = W + (size_t)(k0 + kk)*Nc + col0 + n0;
            #pragma unroll
            for (int j = 0; j < 8; j++) {
                int gn = col0 + n0 + j;
                Ws[kk][n0 + j] = (gn < Nc) ? wrow[j] : 0.f;
            }
        }
        __syncthreads();
        #pragma unroll
        for (int kk = 0; kk < 32; kk++) {
            float a0 = As[ty*2 + 0][kk];
            float a1 = As[ty*2 + 1][kk];
            float4 w4 = *(const float4*)&Ws[kk][tx*4];
            acc[0][0] += a0*w4.x; acc[0][1] += a0*w4.y; acc[0][2] += a0*w4.z; acc[0][3] += a0*w4.w;
            acc[1][0] += a1*w4.x; acc[1][1] += a1*w4.y; acc[1][2] += a1*w4.z; acc[1][3] += a1*w4.w;
        }
        __syncthreads();
    }
    #pragma unroll
    for (int i = 0; i < 2; i++) {
        int gm = row0 + ty*2 + i;
        #pragma unroll
        for (int j = 0; j < 4; j++) {
            int gn = col0 + tx*4 + j;
            if (gn < Nc) out[(size_t)gm*Nc + gn] = acc[i][j] + bias[gn];
        }
    }
}

__global__ void gemm_cat_kernel(const float* __restrict__ A0, int ca,
                                const float* __restrict__ A1, int cb,
                                const float* __restrict__ W, const float* __restrict__ bias,
                                float* __restrict__ out, int Nc)
{
    gemm_body(A0, ca, A1, cb, W, bias, out, Nc);
}

__global__ void gemm_heads_kernel(const float* __restrict__ ctrl,
                                  const float* __restrict__ readW, const float* __restrict__ readb,
                                  float* __restrict__ rp,
                                  const float* __restrict__ writeW, const float* __restrict__ writeb,
                                  float* __restrict__ wp)
{
    int h = blockIdx.z;
    const float *W, *bias; float* out; int Nc;
    if (h < 4) {
        W = readW + (size_t)h*C_*PR_; bias = readb + h*PR_;
        out = rp + (size_t)h*B_*PR_;  Nc = PR_;
    } else {
        int g = h - 4;
        W = writeW + (size_t)g*C_*PW_; bias = writeb + g*PW_;
        out = wp + (size_t)g*B_*PW_;   Nc = PW_;
    }
    gemm_body(ctrl, C_, nullptr, 0, W, bias, out, Nc);
}

// ---------------- Pass A: mem norms + 5 key dots + head-1 base dots ----------------
// Half-warp (16 lanes, float4/lane) per row; 2-row unroll (MLP 4).
__global__ void __launch_bounds__(256) passA_kernel(const float* __restrict__ mem)
{
    int bc = blockIdx.x; int b = bc >> 1; int nb = (bc & 1) << 10;
    int tid = threadIdx.x, wid = tid >> 5, lane = tid & 31;
    int hw = lane >> 4, l16 = lane & 15;

    // Scalar key loads (key rows are NOT 16B aligned: PR_=70, PW_=198)
    float4 kr[5];
    #pragma unroll
    for (int h = 0; h < 5; h++) {
        const float* kp = (h < 4) ? (g_rp + ((size_t)h*B_ + b)*PR_) : (g_wp + (size_t)b*PW_);
        kr[h].x = kp[l16*4 + 0];
        kr[h].y = kp[l16*4 + 1];
        kr[h].z = kp[l16*4 + 2];
        kr[h].w = kp[l16*4 + 3];
    }
    // Head-0 erase/add + head-1 key, per-lane (4 m's each)
    const float* wp0 = g_wp + (size_t)b*PW_;
    const float* wp1 = g_wp + ((size_t)1*B_ + b)*PW_;
    float e0[4], a0[4], k1[4], e0sq[4], e0a0[4], e0k1[4];
    #pragma unroll
    for (int j = 0; j < 4; j++) {
        int m = l16*4 + j;
        e0[j] = sigmoidf(wp0[70 + m]);
        a0[j] = tanhf(wp0[134 + m]);
        k1[j] = wp1[m];
        e0sq[j] = e0[j]*e0[j];
        e0a0[j] = e0[j]*a0[j];
        e0k1[j] = e0[j]*k1[j];
    }

    const float* base = mem + ((size_t)b*N_ + nb)*M_;
    for (int it = 0; it < 64; it += 2) {
        int rA = it*16 + wid*2 + hw;
        int rB = rA + 16;
        float4 va = *(const float4*)(base + (size_t)rA*M_ + l16*4);
        float4 vb = *(const float4*)(base + (size_t)rB*M_ + l16*4);

        // 12 reductions per row
        float accA[12] = {}, accB[12] = {};
        {
            float v[4] = {va.x, va.y, va.z, va.w};
            #pragma unroll
            for (int j = 0; j < 4; j++) {
                float vs = v[j]*v[j];
                accA[0] += vs;
                accA[1] += v[j]*kr[0].x*(j==0) + v[j]*kr[0].y*(j==1) + v[j]*kr[0].z*(j==2) + v[j]*kr[0].w*(j==3);
                // (expanded below instead)
            }
        }
        // explicit accumulation (avoid the awkward select above)
        {
            float v[4]  = {va.x, va.y, va.z, va.w};
            float u[4]  = {vb.x, vb.y, vb.z, vb.w};
            float kk[5][4] = {
                {kr[0].x,kr[0].y,kr[0].z,kr[0].w},
                {kr[1].x,kr[1].y,kr[1].z,kr[1].w},
                {kr[2].x,kr[2].y,kr[2].z,kr[2].w},
                {kr[3].x,kr[3].y,kr[3].z,kr[3].w},
                {kr[4].x,kr[4].y,kr[4].z,kr[4].w}};
            #pragma unroll
            for (int r = 0; r < 12; r++) { accA[r] = 0.f; accB[r] = 0.f; }
            #pragma unroll
            for (int j = 0; j < 4; j++) {
                float vj = v[j], uj = u[j];
                float vs = vj*vj, us = uj*uj;
                accA[0] += vs;               accB[0] += us;                 // norm^2
                #pragma unroll
                for (int h = 0; h < 5; h++) {
                    accA[1+h] += vj*kk[h][j];
                    accB[1+h] += uj*kk[h][j];
                }
                accA[6]  += vj*k1[j];        accB[6]  += uj*k1[j];          // Da
                accA[7]  += vj*e0k1[j];      accB[7]  += uj*e0k1[j];        // Db
                accA[8]  += vs*e0[j];        accB[8]  += us*e0[j];          // S1
                accA[9]  += vs*e0sq[j];      accB[9]  += us*e0sq[j];        // S2
                accA[10] += vj*a0[j];        accB[10] += uj*a0[j];          // T0
                accA[11] += vj*e0a0[j];      accB[11] += uj*e0a0[j];        // T1
            }
        }
        #pragma unroll
        for (int o = 8; o > 0; o >>= 1) {
            #pragma unroll
            for (int r = 0; r < 12; r++) {
                accA[r] += __shfl_xor_sync(0xffffffffu, accA[r], o);
                accB[r] += __shfl_xor_sync(0xffffffffu, accB[r], o);
            }
        }
        if (l16 == 0) {
            size_t ixA = (size_t)b*N_ + nb + rA;
            size_t ixB = (size_t)b*N_ + nb + rB;
            g_norm[ixA] = sqrtf(accA[0]);
            g_norm[ixB] = sqrtf(accB[0]);
            #pragma unroll
            for (int h = 0; h < 5; h++) {
                g_dot[(size_t)h*B_*N_ + ixA] = accA[1+h];
                g_dot[(size_t)h*B_*N_ + ixB] = accB[1+h];
            }
            #pragma unroll
            for (int r = 0; r < 6; r++) {
                g_base[(size_t)r*B_*N_ + ixA] = accA[6+r];
                g_base[(size_t)r*B_*N_ + ixB] = accB[6+r];
            }
        }
    }
}

// ---------------- block reduction helpers (256 threads) ----------------
__device__ __forceinline__ float block_reduce_sum(float v, float* sbuf)
{
    int tid = threadIdx.x;
    #pragma unroll
    for (int o = 16; o > 0; o >>= 1) v += __shfl_xor_sync(0xffffffffu, v, o);
    if ((tid & 31) == 0) sbuf[tid >> 5] = v;
    __syncthreads();
    if (tid < 32) {
        float x = (tid < 8) ? sbuf[tid] : 0.f;
        #pragma unroll
        for (int o = 4; o > 0; o >>= 1) x += __shfl_xor_sync(0xffffffffu, x, o);
        if (tid == 0) sbuf[0] = x;
    }
    __syncthreads();
    float r = sbuf[0];
    __syncthreads();
    return r;
}

__device__ __forceinline__ float block_reduce_max(float v, float* sbuf)
{
    int tid = threadIdx.x;
    #pragma unroll
    for (int o = 16; o > 0; o >>= 1) v = fmaxf(v, __shfl_xor_sync(0xffffffffu, v, o));
    if ((tid & 31) == 0) sbuf[tid >> 5] = v;
    __syncthreads();
    if (tid < 32) {
        float x = (tid < 8) ? sbuf[tid] : -3.4e38f;
        #pragma unroll
        for (int o = 4; o > 0; o >>= 1) x = fmaxf(x, __shfl_xor_sync(0xffffffffu, x, o));
        if (tid == 0) sbuf[0] = x;
    }
    __syncthreads();
    float r = sbuf[0];
    __syncthreads();
    return r;
}

// ---------------- poly kernel: dot/norm for head h from base dots + w_{h-1} ----------------
// he = head providing erase/add (h-1), hk = head providing key (h).
__global__ void poly_kernel(const float* __restrict__ ww, int he, int hk)
{
    int b = blockIdx.x, tid = threadIdx.x;
    __shared__ float rbuf[32];
    const float* pe = g_wp + ((size_t)he*B_ + b)*PW_;
    const float* pk = g_wp + ((size_t)hk*B_ + b)*PW_;
    float c1 = 0.f, c2 = 0.f;
    if (tid < 64) {
        float a = tanhf(pe[134 + tid]);
        float k = pk[tid];
        c1 = a*k; c2 = a*a;
    }
    float Cc = block_reduce_sum(c1, rbuf);
    float U  = block_reduce_sum(c2, rbuf);

    size_t base = (size_t)b*N_;
    float* dotp = g_dot + (size_t)4*B_*N_ + base;
    float* nrmp = g_norm + base;
    const size_t P = (size_t)B_*N_;
    #pragma unroll
    for (int i = 0; i < 8; i++) {
        int n = tid + i*256;
        float w  = ww[base + n];
        float Da = g_base[0*P + base + n];
        float Db = g_base[1*P + base + n];
        float S1 = g_base[2*P + base + n];
        float S2 = g_base[3*P + base + n];
        float T0 = g_base[4*P + base + n];
        float T1 = g_base[5*P + base + n];
        float nr = nrmp[n];
        float S0 = nr*nr;
        float dot1 = Da - w*Db + w*Cc;
        float w2 = w*w;
        float nsq = S0 - 2.f*w*S1 + w2*S2 + 2.f*w*T0 - 2.f*w2*T1 + w2*U;
        dotp[n] = dot1;
        nrmp[n] = sqrtf(fmaxf(nsq, 0.f));
    }
}

// ---------------- NTM addressing body ----------------
__device__ __forceinline__ void address_body(
    const float* __restrict__ p,
    const float* __restrict__ dotb,
    const float* __restrict__ nrmb,
    const float* __restrict__ wpb,
    float* __restrict__ woutb)
{
    int tid = threadIdx.x;
    __shared__ float wg[2048];
    __shared__ float rbuf[32];
    __shared__ float sc[7];

    float kv = 0.f;
    if (tid < 64) { float x = p[tid]; kv = x*x; }
    float ksum = block_reduce_sum(kv, rbuf);
    if (tid == 0) {
        sc[0] = sqrtf(ksum);
        sc[1] = softplusf(p[64]);
        sc[2] = sigmoidf(p[65]);
        float a0 = p[66], a1 = p[67], a2 = p[68];
        float mx = fmaxf(a0, fmaxf(a1, a2));
        float e0 = expf(a0-mx), e1 = expf(a1-mx), e2 = expf(a2-mx);
        float es = e0 + e1 + e2;
        sc[3] = e0/es; sc[4] = e1/es; sc[5] = e2/es;
        sc[6] = 1.f + softplusf(p[69]);
    }
    __syncthreads();
    float knorm = sc[0], beta = sc[1], g = sc[2];
    float s0 = sc[3], s1 = sc[4], s2 = sc[5], gamma = sc[6];

    float x[8];
    float mx = -3.4e38f;
    #pragma unroll
    for (int i = 0; i < 8; i++) {
        int n = tid + i*256;
        float cosv = dotb[n] / (nrmb[n]*knorm + EPSF);
        x[i] = beta * cosv;
        mx = fmaxf(mx, x[i]);
    }
    float bmax = block_reduce_max(mx, rbuf);
    float lsum = 0.f;
    #pragma unroll
    for (int i = 0; i < 8; i++) {
        float e = __expf(x[i] - bmax);
        wg[tid + i*256] = e;
        lsum += e;
    }
    float bsum = block_reduce_sum(lsum, rbuf);
    float inv = 1.f / bsum;
    #pragma unroll
    for (int i = 0; i < 8; i++) {
        int n = tid + i*256;
        wg[n] = g * (wg[n]*inv) + (1.f-g) * wpb[n];
    }
    __syncthreads();
    float wpow[8];
    lsum = 0.f;
    #pragma unroll
    for (int i = 0; i < 8; i++) {
        int n = tid + i*256;
        float ws = s0*wg[(n+1)&(N_-1)] + s1*wg[n] + s2*wg[(n-1)&(N_-1)];
        float t = __powf(ws + EPSF, gamma);
        wpow[i] = t;
        lsum += t;
    }
    float psum = block_reduce_sum(lsum, rbuf);
    float ip = 1.f / psum;
    #pragma unroll
    for (int i = 0; i < 8; i++)
        woutb[tid + i*256] = wpow[i]*ip;
}

__global__ void address5_kernel(const float* __restrict__ prw,
                                const float* __restrict__ pww,
                                float* __restrict__ o_rw,
                                float* __restrict__ o_ww)
{
    int b = blockIdx.x, h = blockIdx.y;
    const float *p, *dotp, *wprev; float* wout;
    if (h < 4) {
        p     = g_rp + ((size_t)h*B_ + b)*PR_;
        dotp  = g_dot + (size_t)h*B_*N_ + (size_t)b*N_;
        wprev = prw  + (size_t)h*B_*N_ + (size_t)b*N_;
        wout  = o_rw + (size_t)h*B_*N_ + (size_t)b*N_;
    } else {
        p     = g_wp + (size_t)b*PW_;
        dotp  = g_dot + (size_t)4*B_*N_ + (size_t)b*N_;
        wprev = pww  + (size_t)b*N_;
        wout  = o_ww + (size_t)b*N_;
    }
    address_body(p, dotp, g_norm + (size_t)b*N_, wprev, wout);
}

__global__ void address1_kernel(int h,
                                const float* __restrict__ pww,
                                float* __restrict__ o_ww)
{
    int b = blockIdx.x;
    address_body(g_wp + ((size_t)h*B_ + b)*PW_,
                 g_dot + (size_t)4*B_*N_ + (size_t)b*N_,
                 g_norm + (size_t)b*N_,
                 pww  + (size_t)h*B_*N_ + (size_t)b*N_,
                 o_ww + (size_t)h*B_*N_ + (size_t)b*N_);
}

// ---------------- Sweep 1: reads einsum + heads 0&1 update + dot2/norm2 + head-3 bases ---------
// Half-warp per row, float4/lane, 2-row unroll.
__global__ void __launch_bounds__(256) sweep1_kernel(
    const float* __restrict__ mem_in, float* __restrict__ mem_out,
    const float* __restrict__ wr,    // new_read_w [4][B][N]
    const float* __restrict__ wwp,   // new_write_w planes (0,1 used)
    float* __restrict__ ro_part)
{
    int bc = blockIdx.x; int b = bc >> 1; int nb = (bc & 1) << 10;
    int tid = threadIdx.x, wid = tid >> 5, lane = tid & 31;
    int hw = lane >> 4, l16 = lane & 15;

    __shared__ float4 sred[8][4][32];

    // per-lane constants (4 m's): heads 0,1 e/a; head2 key,e,a; head3 key
    const float* p0 = g_wp + (size_t)b*PW_;
    const float* p1 = g_wp + ((size_t)1*B_ + b)*PW_;
    const float* p2 = g_wp + ((size_t)2*B_ + b)*PW_;
    const float* p3 = g_wp + ((size_t)3*B_ + b)*PW_;
    float e0[4], a0[4], e1[4], a1[4], k2[4], e2[4], a2[4], k3[4];
    float e2k3[4], e2sq[4], e2a2[4];
    #pragma unroll
    for (int j = 0; j < 4; j++) {
        int m = l16*4 + j;
        e0[j] = sigmoidf(p0[70 + m]);  a0[j] = tanhf(p0[134 + m]);
        e1[j] = sigmoidf(p1[70 + m]);  a1[j] = tanhf(p1[134 + m]);
        k2[j] = p2[m];
        e2[j] = sigmoidf(p2[70 + m]);  a2[j] = tanhf(p2[134 + m]);
        k3[j] = p3[m];
        e2k3[j] = e2[j]*k3[j];
        e2sq[j] = e2[j]*e2[j];
        e2a2[j] = e2[j]*a2[j];
    }

    float4 racc[4] = {{0,0,0,0},{0,0,0,0},{0,0,0,0},{0,0,0,0}};
    const size_t P = (size_t)B_*N_;
    float* dot2p = g_dot + 4*P;

    for (int it = 0; it < 64; it += 2) {
        int rA = it*16 + wid*2 + hw;
        int rB = rA + 16;
        size_t ixA = (size_t)b*N_ + nb + rA;
        size_t ixB = (size_t)b*N_ + nb + rB;

        float4 va = *(const float4*)(mem_in + ixA*M_ + l16*4);
        float4 vb = *(const float4*)(mem_in + ixB*M_ + l16*4);
        float w0A = wwp[ixA],     w0B = wwp[ixB];
        float w1A = wwp[P + ixA], w1B = wwp[P + ixB];
        float wvA[4], wvB[4];
        #pragma unroll
        for (int h = 0; h < 4; h++) {
            wvA[h] = wr[(size_t)h*P + ixA];
            wvB[h] = wr[(size_t)h*P + ixB];
        }

        float v[4]  = {va.x, va.y, va.z, va.w};
        float u[4]  = {vb.x, vb.y, vb.z, vb.w};
        float m2A[4], m2B[4];
        float accA[8] = {}, accB[8] = {};
        #pragma unroll
        for (int j = 0; j < 4; j++) {
            // reads einsum (uses ORIGINAL memory)
            float* ra;
            ra = &racc[0].x; ra[j] += 0.f; // (keep compiler happy about vector access pattern)
            racc[0].x += 0.f;
            // head updates
            float m1a = v[j]*(1.f - w0A*e0[j]) + w0A*a0[j];
            float m1b = u[j]*(1.f - w0B*e0[j]) + w0B*a0[j];
            float m2a = m1a*(1.f - w1A*e1[j]) + w1A*a1[j];
            float m2b = m1b*(1.f - w1B*e1[j]) + w1B*a1[j];
            m2A[j] = m2a; m2B[j] = m2b;
            float sa = m2a*m2a, sb = m2b*m2b;
            accA[0] += m2a*k2[j];    accB[0] += m2b*k2[j];    // dot2
            accA[1] += sa;           accB[1] += sb;           // norm2^2
            accA[2] += m2a*k3[j];    accB[2] += m2b*k3[j];    // Da
            accA[3] += m2a*e2k3[j];  accB[3] += m2b*e2k3[j];  // Db
            accA[4] += sa*e2[j];     accB[4] += sb*e2[j];     // S1
            accA[5] += sa*e2sq[j];   accB[5] += sb*e2sq[j];   // S2
            accA[6] += m2a*a2[j];    accB[6] += m2b*a2[j];    // T0
            accA[7] += m2a*e2a2[j];  accB[7] += m2b*e2a2[j];  // T1
        }
        // reads accumulation (vector form)
        #pragma unroll
        for (int h = 0; h < 4; h++) {
            racc[h].x += wvA[h]*v[0] + wvB[h]*u[0];
            racc[h].y += wvA[h]*v[1] + wvB[h]*u[1];
            racc[h].z += wvA[h]*v[2] + wvB[h]*u[2];
            racc[h].w += wvA[h]*v[3] + wvB[h]*u[3];
        }

        *(float4*)(mem_out + ixA*M_ + l16*4) = make_float4(m2A[0], m2A[1], m2A[2], m2A[3]);
        *(float4*)(mem_out + ixB*M_ + l16*4) = make_float4(m2B[0], m2B[1], m2B[2], m2B[3]);

        #pragma unroll
        for (int o = 8; o > 0; o >>= 1) {
            #pragma unroll
            for (int r = 0; r < 8; r++) {
                accA[r] += __shfl_xor_sync(0xffffffffu, accA[r], o);
                accB[r] += __shfl_xor_sync(0xffffffffu, accB[r], o);
            }
        }
        if (l16 == 0) {
            dot2p[ixA] = accA[0];            dot2p[ixB] = accB[0];
            g_norm[ixA] = sqrtf(accA[1]);    g_norm[ixB] = sqrtf(accB[1]);
            #pragma unroll
            for (int r = 0; r < 6; r++) {
                g_base[(size_t)r*P + ixA] = accA[2+r];
                g_base[(size_t)r*P + ixB] = accB[2+r];
            }
        }
    }

    #pragma unroll
    for (int h = 0; h < 4; h++) sred[wid][h][lane] = racc[h];
    __syncthreads();
    int h = tid >> 6, m = tid & 63;
    int l = m >> 2, c = m & 3;
    float s = 0.f;
    #pragma unroll
    for (int w = 0; w < 8; w++) {
        s += ((const float*)&sred[w][h][l])[c];
        s += ((const float*)&sred[w][h][l + 16])[c];
    }
    ro_part[(size_t)(bc & 1)*B_*256 + (size_t)b*256 + h*64 + m] = s;
}

__global__ void sum_ro_kernel(const float* __restrict__ part, float* __restrict__ o_ro)
{
    int i = blockIdx.x*blockDim.x + threadIdx.x;
    o_ro[i] = part[i] + part[B_*256 + i];
}

// ---------------- Sweep 2: heads 2&3 update in place ----------------
__global__ void __launch_bounds__(256) sweep2_kernel(
    float* __restrict__ memio,
    const float* __restrict__ wwp)   // planes 2,3 used
{
    int bc = blockIdx.x; int b = bc >> 1; int nb = (bc & 1) << 10;
    int tid = threadIdx.x, wid = tid >> 5, lane = tid & 31;

    __shared__ float sE2[64], sA2[64], sE3[64], sA3[64];
    if (tid < 64) {
        const float* p2 = g_wp + ((size_t)2*B_ + b)*PW_;
        const float* p3 = g_wp + ((size_t)3*B_ + b)*PW_;
        sE2[tid] = sigmoidf(p2[70 + tid]);
        sA2[tid] = tanhf(p2[134 + tid]);
        sE3[tid] = sigmoidf(p3[70 + tid]);
        sA3[tid] = tanhf(p3[134 + tid]);
    }
    __syncthreads();
    float e2x = sE2[2*lane], e2y = sE2[2*lane+1];
    float a2x = sA2[2*lane], a2y = sA2[2*lane+1];
    float e3x = sE3[2*lane], e3y = sE3[2*lane+1];
    float a3x = sA3[2*lane], a3y = sA3[2*lane+1];

    const size_t P = (size_t)B_*N_;
    for (int it = 0; it < 32; ++it) {
        size_t wix0 = (size_t)b*N_ + nb + it*32 + wid*4;
        float* base = memio + wix0*M_ + 2*lane;

        float2 v[4];
        v[0] = *(const float2*)(base);
        v[1] = *(const float2*)(base + M_);
        v[2] = *(const float2*)(base + 2*M_);
        v[3] = *(const float2*)(base + 3*M_);
        float w2[4], w3[4];
        #pragma unroll
        for (int r = 0; r < 4; r++) {
            w2[r] = wwp[2*P + wix0 + r];
            w3[r] = wwp[3*P + wix0 + r];
        }
        #pragma unroll
        for (int r = 0; r < 4; r++) {
            float2 u;
            u.x = v[r].x*(1.f - w2[r]*e2x) + w2[r]*a2x;
            u.y = v[r].y*(1.f - w2[r]*e2y) + w2[r]*a2y;
            float2 t;
            t.x = u.x*(1.f - w3[r]*e3x) + w3[r]*a3x;
            t.y = u.y*(1.f - w3[r]*e3y) + w3[r]*a3y;
            *(float2*)(base + (size_t)r*M_) = t;
        }
    }
}

// ---------------- host launcher ----------------
extern "C" void kernel_launch(void* const* d_in, const int* in_sizes, int n_in,
                              void* d_out, int out_size)
{
    const float* ext    = (const float*)d_in[0];
    const float* pread  = (const float*)d_in[1];
    const float* prw    = (const float*)d_in[2];
    const float* pww    = (const float*)d_in[3];
    const float* mem    = (const float*)d_in[4];
    const float* ctrlW  = (const float*)d_in[5];
    const float* ctrlb  = (const float*)d_in[6];
    const float* readW  = (const float*)d_in[7];
    const float* readb  = (const float*)d_in[8];
    const float* writeW = (const float*)d_in[9];
    const float* writeb = (const float*)d_in[10];
    const float* outW   = (const float*)d_in[11];
    const float* outb   = (const float*)d_in[12];
    float* out = (float*)d_out;

    float *ctrl, *rp, *wp, *ropart;
    cudaGetSymbolAddress((void**)&ctrl,   g_ctrl);
    cudaGetSymbolAddress((void**)&rp,     g_rp);
    cudaGetSymbolAddress((void**)&wp,     g_wp);
    cudaGetSymbolAddress((void**)&ropart, g_ropart);

    float* o_mem = out + OUT_MEM;
    float* o_ro  = out + OUT_RO;
    float* o_rw  = out + OUT_RW;
    float* o_ww  = out + OUT_WW;

    // Controller GEMM with fused concat
    gemm_cat_kernel<<<dim3(8, 8), 256>>>(ext, 256, pread, 256, ctrlW, ctrlb, ctrl, 512);

    // All 8 head parameter GEMMs in one launch
    gemm_heads_kernel<<<dim3(4, 8, 8), 256>>>(ctrl, readW, readb, rp, writeW, writeb, wp);

    // Pass A: norms + dots (reads + write head0) + head-1 base dots
    passA_kernel<<<512, 256>>>(mem);

    // Addressing for 4 read heads + write head 0 (fused)
    address5_kernel<<<dim3(256, 5), 256>>>(prw, pww, o_rw, o_ww);

    // dot1/norm1 from bases + w0; addressing head 1
    poly_kernel<<<256, 256>>>(o_ww, 0, 1);
    address1_kernel<<<256, 256>>>(1, pww, o_ww);

    // Sweep 1: reads einsum + heads 0&1 update + dot2/norm2 + head-3 bases
    sweep1_kernel<<<512, 256>>>(mem, o_mem, o_rw, o_ww, ropart);
    sum_ro_kernel<<<64, 1024>>>(ropart, o_ro);

    // addressing head 2; dot3/norm3 from bases + w2; addressing head 3
    address1_kernel<<<256, 256>>>(2, pww, o_ww);
    poly_kernel<<<256, 256>>>(o_ww + (size_t)2*B_*N_, 2, 3);
    address1_kernel<<<256, 256>>>(3, pww, o_ww);

    // Sweep 2: heads 2&3 update in place
    sweep2_kernel<<<512, 256>>>(o_mem, o_ww);

    // Output GEMM with fused concat
    gemm_cat_kernel<<<dim3(4, 8), 256>>>(ctrl, 512, o_ro, 256, outW, outb, out, 256);
}